// round 10
// baseline (speedup 1.0000x reference)
#include <cuda_runtime.h>
#include <cstdint>

#define NIN      2049   // inputs per frame
#define NOUT     1024   // outputs per frame
#define ROWS     12     // frames per CTA -> grid = 134 (single wave)
#define THREADS  1024

__device__ __forceinline__ void cp16(uint32_t dst, const void* src) {
    asm volatile("cp.async.cg.shared.global [%0], [%1], 16;"
                 :: "r"(dst), "l"(src) : "memory");
}

__global__ void __launch_bounds__(THREADS)
logscale_kernel(const float* __restrict__ x,
                const float* __restrict__ frac,
                const float* __restrict__ cubt,
                const float* __restrict__ triw,
                const int*   __restrict__ pair,
                const int*   __restrict__ cubi,
                const int*   __restrict__ tridx,
                float* __restrict__ out,
                int n_rows, int n_lin, int n_cub, int max_w, int n_tri)
{
    // Shared: sx[ROWS*NIN] | swt[n_tri*wstride] | si0[n_tri]
    extern __shared__ float smem_pool[];
    const int wstride = ((max_w + 4) >> 2) << 2;   // 44 for max_w=40 (16B mult)
    float* sx  = smem_pool;
    float* swt = smem_pool + ROWS * NIN;
    int*   si0 = (int*)(swt + n_tri * wstride);

    const int row0  = blockIdx.x * ROWS;
    const int nr    = min(ROWS, n_rows - row0);
    const int t     = threadIdx.x;
    const int n_sum = n_lin + n_cub;
    const float NEG_INF = __int_as_float(0xff800000);

    const uint32_t sbase = (uint32_t)__cvta_generic_to_shared(smem_pool);

    // ---- 1) Issue async staging (x tile + tri weights), non-blocking ----
    {
        const int nv = (nr * NIN) >> 2;            // nr*NIN % 4 == 0 (nr in {12,4})
        const float4* s4 = (const float4*)(x + (size_t)row0 * NIN);
        #pragma unroll
        for (int u = 0; u < 7; u++) {
            const int i = t + u * THREADS;
            if (i < nv) cp16(sbase + i * 16, s4 + i);
        }
        if ((max_w & 3) == 0) {                    // 16B-chunk path (max_w=40)
            const int chunks = max_w >> 2;
            const int ctot   = n_tri * chunks;
            const uint32_t swt_b = sbase + ROWS * NIN * 4;
            for (int i = t; i < ctot; i += THREADS) {
                const int j = i / chunks;
                const int c = i - j * chunks;
                cp16(swt_b + (uint32_t)(j * wstride + c * 4) * 4,
                     triw + (size_t)j * max_w + c * 4);
            }
        } else {                                   // generic fallback
            const int wtot = n_tri * max_w;
            for (int i = t; i < wtot; i += THREADS) {
                const int j = i / max_w;
                const int w = i - j * max_w;
                swt[j * wstride + w] = __ldg(triw + i);
            }
        }
        asm volatile("cp.async.commit_group;" ::: "memory");
    }

    // ---- 2) Low threads (no Phase-A work) fetch tri window starts ----
    if (t < n_tri)
        si0[t] = __ldg(tridx + (size_t)t * max_w); // first entry always valid

    // ---- 3) Phase A: linear + cubic straight from GLOBAL (overlaps DMA) --
    // Highest threads own these columns; warps contiguous in o -> coalesced
    // stores; x windows are contiguous per warp -> L1-friendly.
    {
        const int o = t - (THREADS - n_sum);
        if (o >= 0) {
            if (o < n_lin) {
                const int   i0 = __ldg(pair + o);
                const float f  = __ldg(frac + o);
                #pragma unroll
                for (int r = 0; r < ROWS; r++) {
                    const int rr = min(row0 + r, n_rows - 1);   // clamp: no OOB reads
                    const float* xr = x + (size_t)rr * NIN;
                    const float x0 = __ldg(xr + i0);
                    const float x1 = __ldg(xr + i0 + 1);
                    if (r < nr)
                        out[(size_t)(row0 + r) * NOUT + o] = x0 + f * (x1 - x0);
                }
            } else {
                const int   j  = o - n_lin;
                const int   i0 = __ldg(cubi + j);
                const float tc = __ldg(cubt + j);
                #pragma unroll 4
                for (int r = 0; r < ROWS; r++) {
                    const int rr = min(row0 + r, n_rows - 1);
                    const float* xr = x + (size_t)rr * NIN;
                    const float xm1 = __ldg(xr + i0 - 1);
                    const float x0  = __ldg(xr + i0);
                    const float x1  = __ldg(xr + i0 + 1);
                    const float x2  = __ldg(xr + i0 + 2);
                    const float v = x0 + 0.5f * tc * (x1 - xm1
                                  + tc * (2.0f * xm1 - 5.0f * x0 + 4.0f * x1 - x2
                                  + tc * (3.0f * (x0 - x1) + x2 - xm1)));
                    if (r < nr)
                        out[(size_t)(row0 + r) * NOUT + o] = v;
                }
            }
        }
    }

    // ---- 4) Wait for staging, make it CTA-visible ----
    asm volatile("cp.async.wait_group 0;" ::: "memory");
    __syncthreads();

    // ---- 5) Triangular: task = (j, row-quarter), j descending -----------
    // Longest windows go to the lowest threads (which had no Phase-A work).
    // 3 independent max chains per task; padded weights are exactly -inf
    // (valid ones bottom at -160 dB) -> batch-4 early exit, branch-light.
    for (int task = t; task < 4 * n_tri; task += THREADS) {
        const int j   = n_tri - 1 - (task >> 2);
        const int q3  = (task & 3) * 3;
        const int i0  = si0[j];
        const float* __restrict__ wp = swt + j * wstride;
        const float* __restrict__ p  = sx + q3 * NIN + i0;

        float m0 = NEG_INF, m1 = NEG_INF, m2 = NEG_INF;
        bool done = false;
        for (int wb = 0; wb < max_w && !done; wb += 4) {
            float wv[4];
            #pragma unroll
            for (int c = 0; c < 4; c++)
                wv[c] = (wb + c < max_w) ? wp[wb + c] : NEG_INF;
            #pragma unroll
            for (int c = 0; c < 4; c++) {
                if (__float_as_int(wv[c]) == (int)0xff800000) { done = true; break; }
                m0 = fmaxf(m0, p[wb + c]           + wv[c]);
                m1 = fmaxf(m1, p[NIN + wb + c]     + wv[c]);
                m2 = fmaxf(m2, p[2 * NIN + wb + c] + wv[c]);
            }
        }
        const int o = n_sum + j;
        if (q3 + 0 < nr) out[(size_t)(row0 + q3 + 0) * NOUT + o] = m0;
        if (q3 + 1 < nr) out[(size_t)(row0 + q3 + 1) * NOUT + o] = m1;
        if (q3 + 2 < nr) out[(size_t)(row0 + q3 + 2) * NOUT + o] = m2;
    }
}

extern "C" void kernel_launch(void* const* d_in, const int* in_sizes, int n_in,
                              void* d_out, int out_size)
{
    const float* x     = (const float*)d_in[0];
    const float* frac  = (const float*)d_in[1];
    const float* cubt  = (const float*)d_in[2];
    const float* triw  = (const float*)d_in[3];
    const int*   pair  = (const int*)d_in[4];
    const int*   cubi  = (const int*)d_in[5];
    const int*   tridx = (const int*)d_in[6];
    float* out = (float*)d_out;

    const int n_lin  = in_sizes[1];
    const int n_cub  = in_sizes[2];
    const int n_tri  = NOUT - n_lin - n_cub;
    const int max_w  = (n_tri > 0) ? in_sizes[3] / n_tri : 0;
    const int n_rows = in_sizes[0] / NIN;
    const int wstride = ((max_w + 4) >> 2) << 2;

    // smem: x tile + padded weights + i0  (~139 KB, opt-in)
    const int smem = (ROWS * NIN + n_tri * wstride + n_tri) * (int)sizeof(float);
    cudaFuncSetAttribute(logscale_kernel,
                         cudaFuncAttributeMaxDynamicSharedMemorySize, smem);

    const int grid = (n_rows + ROWS - 1) / ROWS;   // 134 CTAs for 1600 rows
    logscale_kernel<<<grid, THREADS, smem>>>(x, frac, cubt, triw,
                                             pair, cubi, tridx, out,
                                             n_rows, n_lin, n_cub, max_w, n_tri);
}